// round 1
// baseline (speedup 1.0000x reference)
#include <cuda_runtime.h>
#include <math.h>

// ---------------- problem constants ----------------
#define NN   512     // nodes
#define BB   64      // batch
#define LL   12      // encoder steps
#define HH   12      // decoder steps
#define RNN  64      // encoder hidden
#define DDEC 128     // decoder hidden
#define KENC 390     // 6*(1+64)
#define KDEC 804     // 6*(1+5+128)
#define ROWS (NN*BB) // 32768

// ---------------- scratch (device globals; no allocation) ----------------
__device__ float g_S[4*NN*NN];        // stacked supports: [g1, 2g1^2-I, g2, 2g2^2-I]
__device__ float g_e1[NN*64];
__device__ float g_e2[NN*64];
__device__ float g_xT[NN*LL*BB];      // x as (n, l, b)
__device__ float g_GX[4*NN*LL*BB];    // S_j @ x, (4N, L*B)
__device__ float g_xg[ROWS*KDEC];     // agcn feature buffer (row=(n,b), K cols)
__device__ float g_henc[ROWS*RNN];
__device__ float g_hdec[ROWS*DDEC];
__device__ float g_z [ROWS*DDEC];
__device__ float g_r [ROWS*DDEC];
__device__ float g_hc[ROWS*DDEC];
__device__ float g_zh[ROWS*DDEC];
__device__ float g_go[ROWS];
__device__ float g_Ggo[4*NN*BB];

// ---------------- generic tiled SGEMM, 128x128x8, 8x8 microtile ----------------
// MODE 0: C[r*N+c] = acc                       (plain row-major)
// MODE 1: C[r*N+c] = 2*acc - (r==c)            (Chebyshev T2)
// MODE 2: v = sigmoid(acc + bias[c]); c<splitN -> C (z), else -> C2 (r)
// MODE 3: C[r*N+c] = tanh(acc + bias[c])
// MODE 4: scatter graph-conv result into xg:
//         row = j*512+n, col = b*hd+c  ->  xg[(n*BB+b)*Ktot + off_j + c]
template<int MODE>
__global__ void __launch_bounds__(256)
sgemm(const float* __restrict__ A, const float* __restrict__ Bm, float* __restrict__ C,
      int M, int N, int K, const float* __restrict__ bias, float* __restrict__ C2,
      int splitN, int hdshift, int Ktot, int o0, int o1, int o2, int o3)
{
    __shared__ float As[8][132];
    __shared__ float Bs[8][132];
    const int tid = threadIdx.x;
    const int tx  = tid & 15;
    const int ty  = tid >> 4;
    const int row0 = blockIdx.y * 128;
    const int col0 = blockIdx.x * 128;

    float acc[8][8];
    #pragma unroll
    for (int i = 0; i < 8; i++)
        #pragma unroll
        for (int j = 0; j < 8; j++) acc[i][j] = 0.f;

    const int am  = tid >> 1;          // 0..127 (A tile row)
    const int ak0 = (tid & 1) << 2;    // 0 or 4
    const int bk  = tid >> 5;          // 0..7   (B tile row)
    const int bn  = (tid & 31) << 2;   // 0..124 (B tile col)

    for (int k0 = 0; k0 < K; k0 += 8) {
        #pragma unroll
        for (int i = 0; i < 4; i++) {
            int gk = k0 + ak0 + i;
            As[ak0 + i][am] = (gk < K) ? A[(row0 + am) * K + gk] : 0.f;
        }
        {
            int gk = k0 + bk;
            int gn = col0 + bn;
            float4 v = make_float4(0.f, 0.f, 0.f, 0.f);
            if (gk < K && gn < N)
                v = *reinterpret_cast<const float4*>(Bm + gk * N + gn);
            Bs[bk][bn + 0] = v.x; Bs[bk][bn + 1] = v.y;
            Bs[bk][bn + 2] = v.z; Bs[bk][bn + 3] = v.w;
        }
        __syncthreads();
        #pragma unroll
        for (int kk = 0; kk < 8; kk++) {
            float a[8], b[8];
            #pragma unroll
            for (int i = 0; i < 8; i++) a[i] = As[kk][ty * 8 + i];
            #pragma unroll
            for (int j = 0; j < 8; j++) b[j] = Bs[kk][tx * 8 + j];
            #pragma unroll
            for (int i = 0; i < 8; i++)
                #pragma unroll
                for (int j = 0; j < 8; j++)
                    acc[i][j] = fmaf(a[i], b[j], acc[i][j]);
        }
        __syncthreads();
    }

    if (MODE == 4) {
        int j   = row0 >> 9;
        int off = (j == 0) ? o0 : (j == 1) ? o1 : (j == 2) ? o2 : o3;
        int hmask = (1 << hdshift) - 1;
        #pragma unroll
        for (int i = 0; i < 8; i++) {
            int r = row0 + ty * 8 + i;
            int n = r & (NN - 1);
            #pragma unroll
            for (int jj = 0; jj < 8; jj++) {
                int cc = col0 + tx * 8 + jj;
                if (cc < N) {
                    int b = cc >> hdshift;
                    int c = cc & hmask;
                    C[(n * BB + b) * Ktot + off + c] = acc[i][jj];
                }
            }
        }
    } else {
        #pragma unroll
        for (int i = 0; i < 8; i++) {
            int r = row0 + ty * 8 + i;
            #pragma unroll
            for (int jj = 0; jj < 8; jj++) {
                int cc = col0 + tx * 8 + jj;
                if (cc >= N) continue;
                float v = acc[i][jj];
                if (MODE == 0) {
                    C[r * N + cc] = v;
                } else if (MODE == 1) {
                    C[r * N + cc] = 2.f * v - ((r == cc) ? 1.f : 0.f);
                } else if (MODE == 2) {
                    v = 1.f / (1.f + expf(-(v + bias[cc])));
                    if (cc < splitN) C [r * splitN + cc]          = v;
                    else             C2[r * splitN + (cc - splitN)] = v;
                } else { // MODE 3
                    C[r * N + cc] = tanhf(v + bias[cc]);
                }
            }
        }
    }
}

// ---------------- small kernels ----------------
__global__ void k_zero(float* p, int n) {
    int i = blockIdx.x * blockDim.x + threadIdx.x;
    if (i < n) p[i] = 0.f;
}

// e = We(512x20) @ Memory(20x64)
__global__ void k_eW(const float* __restrict__ We, const float* __restrict__ Mem,
                     float* __restrict__ e) {
    int idx = blockIdx.x * blockDim.x + threadIdx.x;
    if (idx >= NN * 64) return;
    int n = idx >> 6, d = idx & 63;
    float s = 0.f;
    #pragma unroll
    for (int k = 0; k < 20; k++) s += We[n * 20 + k] * Mem[k * 64 + d];
    e[idx] = s;
}

// g = softmax(relu(ea @ eb^T)) rows; one block per row, 128 threads
__global__ void k_gsoftmax(const float* __restrict__ ea, const float* __restrict__ eb,
                           float* __restrict__ g) {
    __shared__ float er[64];
    __shared__ float buf[NN];
    __shared__ float red[128];
    int n = blockIdx.x, tid = threadIdx.x;
    if (tid < 64) er[tid] = ea[n * 64 + tid];
    __syncthreads();
    for (int m = tid; m < NN; m += 128) {
        float s = 0.f;
        #pragma unroll
        for (int d = 0; d < 64; d++) s += er[d] * eb[m * 64 + d];
        buf[m] = s > 0.f ? s : 0.f;
    }
    __syncthreads();
    float mx = -1e30f;
    for (int m = tid; m < NN; m += 128) mx = fmaxf(mx, buf[m]);
    red[tid] = mx; __syncthreads();
    for (int s = 64; s > 0; s >>= 1) { if (tid < s) red[tid] = fmaxf(red[tid], red[tid + s]); __syncthreads(); }
    mx = red[0]; __syncthreads();
    float sm = 0.f;
    for (int m = tid; m < NN; m += 128) { float e = expf(buf[m] - mx); buf[m] = e; sm += e; }
    red[tid] = sm; __syncthreads();
    for (int s = 64; s > 0; s >>= 1) { if (tid < s) red[tid] += red[tid + s]; __syncthreads(); }
    float inv = 1.f / red[0];
    for (int m = tid; m < NN; m += 128) g[n * NN + m] = buf[m] * inv;
}

// x (B,1,N,L) -> xT (n, l, b)
__global__ void k_xT(const float* __restrict__ x, float* __restrict__ xT) {
    int idx = blockIdx.x * blockDim.x + threadIdx.x;
    if (idx >= BB * NN * LL) return;
    int l = idx % LL;
    int n = (idx / LL) % NN;
    int b = idx / (LL * NN);
    xT[(n * LL + l) * BB + b] = x[idx];
}

// fill encoder x-channels of xg for step l (cols {0,65,130,195,260,325})
__global__ void k_fill_enc_x(float* __restrict__ xg, const float* __restrict__ xT,
                             const float* __restrict__ GX, int l) {
    int row = blockIdx.x * blockDim.x + threadIdx.x;
    if (row >= ROWS) return;
    int n = row >> 6, b = row & 63;
    float xv = xT[(n * LL + l) * BB + b];
    float* p = xg + row * KENC;
    p[0]   = xv;
    p[195] = xv;
    p[65]  = GX[(0 * NN + n) * (LL * BB) + l * BB + b];
    p[130] = GX[(1 * NN + n) * (LL * BB) + l * BB + b];
    p[260] = GX[(2 * NN + n) * (LL * BB) + l * BB + b];
    p[325] = GX[(3 * NN + n) * (LL * BB) + l * BB + b];
}

// fill identity-support h-channels of xg (blocks k=0 and k=3)
__global__ void k_fill_h_id(float* __restrict__ xg, const float* __restrict__ h,
                            int hdshift, int Ktot, int off0, int off3, int total) {
    int i = blockIdx.x * blockDim.x + threadIdx.x;
    if (i >= total) return;
    int row = i >> hdshift;
    int c   = i & ((1 << hdshift) - 1);
    float v = h[i];
    float* p = xg + row * Ktot;
    p[off0 + c] = v;
    p[off3 + c] = v;
}

// fill decoder go + ycov channels for step t (ycov: row-sum-1 trick -> broadcast)
__global__ void k_fill_dec(float* __restrict__ xg, const float* __restrict__ go,
                           const float* __restrict__ Ggo, const float* __restrict__ tt, int t) {
    int row = blockIdx.x * blockDim.x + threadIdx.x;
    if (row >= ROWS) return;
    int n = row >> 6, b = row & 63;
    float* p = xg + row * KDEC;
    float gv = go[row];
    p[0]   = gv;
    p[402] = gv;
    p[134] = Ggo[(0 * NN + n) * BB + b];
    p[268] = Ggo[(1 * NN + n) * BB + b];
    p[536] = Ggo[(2 * NN + n) * BB + b];
    p[670] = Ggo[(3 * NN + n) * BB + b];
    #pragma unroll
    for (int c = 0; c < 5; c++) {
        float v = tt[(b * 5 + c) * HH + t];
        p[1 + c] = v; p[135 + c] = v; p[269 + c] = v;
        p[403 + c] = v; p[537 + c] = v; p[671 + c] = v;
    }
}

__global__ void k_zh(const float* __restrict__ z, const float* __restrict__ h,
                     float* __restrict__ zh, int n) {
    int i = blockIdx.x * blockDim.x + threadIdx.x;
    if (i < n) zh[i] = z[i] * h[i];
}

__global__ void k_hupd(const float* __restrict__ r, const float* __restrict__ hc,
                       float* __restrict__ h, int n) {
    int i = blockIdx.x * blockDim.x + threadIdx.x;
    if (i < n) { float rv = r[i]; h[i] = rv * h[i] + (1.f - rv) * hc[i]; }
}

// attention over memory; one block per (n,b) row, 64 threads
__global__ void k_attn(const float* __restrict__ h, const float* __restrict__ Wq,
                       const float* __restrict__ Mem, float* __restrict__ hde) {
    __shared__ float hr[64];
    __shared__ float q[64];
    __shared__ float sc[20];
    int row = blockIdx.x, tid = threadIdx.x;
    hr[tid] = h[row * 64 + tid];
    __syncthreads();
    float s = 0.f;
    #pragma unroll
    for (int c = 0; c < 64; c++) s += hr[c] * Wq[c * 64 + tid];
    q[tid] = s;
    __syncthreads();
    if (tid < 20) {
        float v = 0.f;
        #pragma unroll
        for (int c = 0; c < 64; c++) v += q[c] * Mem[tid * 64 + c];
        sc[tid] = v;
    }
    __syncthreads();
    if (tid == 0) {
        float mx = -1e30f;
        for (int j = 0; j < 20; j++) mx = fmaxf(mx, sc[j]);
        float sm = 0.f;
        for (int j = 0; j < 20; j++) { sc[j] = expf(sc[j] - mx); sm += sc[j]; }
        float inv = 1.f / sm;
        for (int j = 0; j < 20; j++) sc[j] *= inv;
    }
    __syncthreads();
    float ha = 0.f;
    #pragma unroll
    for (int j = 0; j < 20; j++) ha += sc[j] * Mem[j * 64 + tid];
    hde[row * 128 + tid]      = hr[tid];
    hde[row * 128 + 64 + tid] = ha;
}

// decoder h update + projection + output write; one block per row, 128 threads
__global__ void k_hupd_dec(const float* __restrict__ r, const float* __restrict__ hc,
                           float* __restrict__ h, const float* __restrict__ pW,
                           const float* __restrict__ pb, float* __restrict__ go,
                           float* __restrict__ out, int t) {
    __shared__ float red[128];
    int row = blockIdx.x, c = threadIdx.x;
    int i = row * 128 + c;
    float rv = r[i];
    float hn = rv * h[i] + (1.f - rv) * hc[i];
    h[i] = hn;
    red[c] = hn * pW[c];
    __syncthreads();
    for (int s = 64; s > 0; s >>= 1) { if (c < s) red[c] += red[c + s]; __syncthreads(); }
    if (c == 0) {
        float g = red[0] + pb[0];
        go[row] = g;
        int n = row >> 6, b = row & 63;
        out[(b * NN + n) * HH + t] = g;
    }
}

// ---------------- host side ----------------
static void launch_gemm(int mode, const float* A, const float* B, float* C,
                        int M, int N, int K,
                        const float* bias = nullptr, float* C2 = nullptr, int splitN = 0,
                        int hdshift = 0, int Ktot = 0,
                        int o0 = 0, int o1 = 0, int o2 = 0, int o3 = 0)
{
    dim3 grid((N + 127) / 128, (M + 127) / 128);
    switch (mode) {
        case 0: sgemm<0><<<grid, 256>>>(A, B, C, M, N, K, bias, C2, splitN, hdshift, Ktot, o0, o1, o2, o3); break;
        case 1: sgemm<1><<<grid, 256>>>(A, B, C, M, N, K, bias, C2, splitN, hdshift, Ktot, o0, o1, o2, o3); break;
        case 2: sgemm<2><<<grid, 256>>>(A, B, C, M, N, K, bias, C2, splitN, hdshift, Ktot, o0, o1, o2, o3); break;
        case 3: sgemm<3><<<grid, 256>>>(A, B, C, M, N, K, bias, C2, splitN, hdshift, Ktot, o0, o1, o2, o3); break;
        case 4: sgemm<4><<<grid, 256>>>(A, B, C, M, N, K, bias, C2, splitN, hdshift, Ktot, o0, o1, o2, o3); break;
    }
}

extern "C" void kernel_launch(void* const* d_in, const int* in_sizes, int n_in,
                              void* d_out, int out_size)
{
    const float* x   = (const float*)d_in[0];
    const float* tt  = (const float*)d_in[3];
    const float* Mem = (const float*)d_in[5];
    const float* Wq  = (const float*)d_in[6];
    const float* We1 = (const float*)d_in[7];
    const float* We2 = (const float*)d_in[8];
    const float* egW = (const float*)d_in[9];
    const float* egb = (const float*)d_in[10];
    const float* euW = (const float*)d_in[11];
    const float* eub = (const float*)d_in[12];
    const float* dgW = (const float*)d_in[13];
    const float* dgb = (const float*)d_in[14];
    const float* duW = (const float*)d_in[15];
    const float* dub = (const float*)d_in[16];
    const float* pW  = (const float*)d_in[17];
    const float* pb  = (const float*)d_in[18];
    float* out = (float*)d_out;

    float *S, *e1, *e2, *xT, *GX, *xg, *henc, *hdec, *z, *r, *hc, *zh, *go, *Ggo;
    cudaGetSymbolAddress((void**)&S,    g_S);
    cudaGetSymbolAddress((void**)&e1,   g_e1);
    cudaGetSymbolAddress((void**)&e2,   g_e2);
    cudaGetSymbolAddress((void**)&xT,   g_xT);
    cudaGetSymbolAddress((void**)&GX,   g_GX);
    cudaGetSymbolAddress((void**)&xg,   g_xg);
    cudaGetSymbolAddress((void**)&henc, g_henc);
    cudaGetSymbolAddress((void**)&hdec, g_hdec);
    cudaGetSymbolAddress((void**)&z,    g_z);
    cudaGetSymbolAddress((void**)&r,    g_r);
    cudaGetSymbolAddress((void**)&hc,   g_hc);
    cudaGetSymbolAddress((void**)&zh,   g_zh);
    cudaGetSymbolAddress((void**)&go,   g_go);
    cudaGetSymbolAddress((void**)&Ggo,  g_Ggo);

    // --- supports ---
    k_eW<<<(NN * 64 + 255) / 256, 256>>>(We1, Mem, e1);
    k_eW<<<(NN * 64 + 255) / 256, 256>>>(We2, Mem, e2);
    k_gsoftmax<<<NN, 128>>>(e1, e2, S);                   // g1 -> block 0
    k_gsoftmax<<<NN, 128>>>(e2, e1, S + 2 * NN * NN);     // g2 -> block 2
    launch_gemm(1, S,              S,              S + 1 * NN * NN, NN, NN, NN); // 2g1^2-I
    launch_gemm(1, S + 2 * NN * NN, S + 2 * NN * NN, S + 3 * NN * NN, NN, NN, NN); // 2g2^2-I

    // --- encoder x precompute ---
    k_xT<<<(BB * NN * LL + 255) / 256, 256>>>(x, xT);
    launch_gemm(0, S, xT, GX, 4 * NN, LL * BB, NN);

    // --- init states ---
    k_zero<<<(ROWS * RNN + 255) / 256, 256>>>(henc, ROWS * RNN);
    k_zero<<<(ROWS + 255) / 256, 256>>>(go, ROWS);

    // --- encoder ---
    for (int l = 0; l < LL; l++) {
        k_fill_enc_x<<<ROWS / 256, 256>>>(xg, xT, GX, l);
        k_fill_h_id<<<(ROWS * RNN) / 256, 256>>>(xg, henc, 6, KENC, 1, 196, ROWS * RNN);
        launch_gemm(4, S, henc, xg, 4 * NN, BB * RNN, NN, nullptr, nullptr, 0,
                    6, KENC, 66, 131, 261, 326);
        launch_gemm(2, xg, egW, z, ROWS, 2 * RNN, KENC, egb, r, RNN);
        k_zh<<<(ROWS * RNN) / 256, 256>>>(z, henc, zh, ROWS * RNN);
        k_fill_h_id<<<(ROWS * RNN) / 256, 256>>>(xg, zh, 6, KENC, 1, 196, ROWS * RNN);
        launch_gemm(4, S, zh, xg, 4 * NN, BB * RNN, NN, nullptr, nullptr, 0,
                    6, KENC, 66, 131, 261, 326);
        launch_gemm(3, xg, euW, hc, ROWS, RNN, KENC, eub);
        k_hupd<<<(ROWS * RNN) / 256, 256>>>(r, hc, henc, ROWS * RNN);
    }

    // --- memory attention -> decoder initial hidden ---
    k_attn<<<ROWS, 64>>>(henc, Wq, Mem, hdec);

    // --- decoder ---
    for (int t = 0; t < HH; t++) {
        launch_gemm(0, S, go, Ggo, 4 * NN, BB, NN);
        k_fill_dec<<<ROWS / 256, 256>>>(xg, go, Ggo, tt, t);
        k_fill_h_id<<<(ROWS * DDEC) / 256, 256>>>(xg, hdec, 7, KDEC, 6, 408, ROWS * DDEC);
        launch_gemm(4, S, hdec, xg, 4 * NN, BB * DDEC, NN, nullptr, nullptr, 0,
                    7, KDEC, 140, 274, 542, 676);
        launch_gemm(2, xg, dgW, z, ROWS, 2 * DDEC, KDEC, dgb, r, DDEC);
        k_zh<<<(ROWS * DDEC) / 256, 256>>>(z, hdec, zh, ROWS * DDEC);
        k_fill_h_id<<<(ROWS * DDEC) / 256, 256>>>(xg, zh, 7, KDEC, 6, 408, ROWS * DDEC);
        launch_gemm(4, S, zh, xg, 4 * NN, BB * DDEC, NN, nullptr, nullptr, 0,
                    7, KDEC, 140, 274, 542, 676);
        launch_gemm(3, xg, duW, hc, ROWS, DDEC, KDEC, dub);
        k_hupd_dec<<<ROWS, 128>>>(r, hc, hdec, pW, pb, go, out, t);
    }
}

// round 2
// speedup vs baseline: 1.2900x; 1.2900x over previous
#include <cuda_runtime.h>
#include <math.h>

// ---------------- problem constants ----------------
#define NN   512     // nodes
#define BB   64      // batch
#define LL   12      // encoder steps
#define HH   12      // decoder steps
#define RNN  64      // encoder hidden
#define DDEC 128     // decoder hidden
#define KENC 390     // 6*(1+64)  (logical)
#define KENC_P 400   // padded to mult of 16
#define KDEC 804     // 6*(1+5+128)
#define KDEC_P 816
#define ROWS (NN*BB) // 32768

// ---------------- scratch (device globals; zero-init, no allocation) ----------------
__device__ float g_S[4*NN*NN];        // stacked supports: [g1, 2g1^2-I, g2, 2g2^2-I]
__device__ float g_e1[NN*64];
__device__ float g_e2[NN*64];
__device__ float g_xT[NN*LL*BB];      // x as (n, l, b)
__device__ float g_GX[4*NN*LL*BB];    // S_j @ x, (4N, L*B)
__device__ float g_xg[ROWS*KDEC_P];   // agcn feature buffer (row=(n,b), padded K cols)
__device__ float g_henc[ROWS*RNN];
__device__ float g_hdec[ROWS*DDEC];
__device__ float g_z [ROWS*DDEC];
__device__ float g_r [ROWS*DDEC];
__device__ float g_hc[ROWS*DDEC];
__device__ float g_zh[ROWS*DDEC];
__device__ float g_go[ROWS];
__device__ float g_Ggo[4*NN*BB];
// zero-padded weight copies (pad rows remain 0 from zero-init)
__device__ float g_egWp[KENC_P*128];
__device__ float g_euWp[KENC_P*64];
__device__ float g_dgWp[KDEC_P*256];
__device__ float g_duWp[KDEC_P*128];

// ---------------- packed f32x2 helpers ----------------
__device__ __forceinline__ void fma2(unsigned long long &d, unsigned long long a, unsigned long long b) {
    asm("fma.rn.f32x2 %0, %1, %2, %0;" : "+l"(d) : "l"(a), "l"(b));
}
__device__ __forceinline__ unsigned long long bcast2(float x) {
    unsigned long long r;
    asm("mov.b64 %0, {%1, %1};" : "=l"(r) : "f"(x));
    return r;
}

// ---------------- tiled SGEMM, 128x128x16, f32x2 FMA, double-buffered ----------------
// Requires: M % 128 == 0, K % 16 == 0. N guarded.
// MODE 0: C[r*N+c] = acc
// MODE 1: C[r*N+c] = 2*acc - (r==c)            (Chebyshev T2)
// MODE 2: v = sigmoid(acc + bias[c]); c<splitN -> C (z), else -> C2 (r)
// MODE 3: C[r*N+c] = tanh(acc + bias[c])
// MODE 4: scatter graph-conv result into xg:
//         row = j*512+n, col = b*hd+c  ->  xg[(n*BB+b)*Ktot + off_j + c]
template<int MODE>
__global__ void __launch_bounds__(256)
sgemm(const float* __restrict__ A, const float* __restrict__ Bm, float* __restrict__ C,
      int M, int N, int K, const float* __restrict__ bias, float* __restrict__ C2,
      int splitN, int hdshift, int Ktot, int o0, int o1, int o2, int o3)
{
    __shared__ __align__(16) float As[2][16][132];
    __shared__ __align__(16) float Bs[2][16][132];
    const int tid = threadIdx.x;
    const int tx  = tid & 15;
    const int ty  = tid >> 4;
    const int row0 = blockIdx.y * 128;
    const int col0 = blockIdx.x * 128;

    const int am  = tid >> 1;          // 0..127 (A tile row)
    const int ak0 = (tid & 1) << 2;    // 0 or 4
    const int bk  = tid >> 5;          // 0..7   (B tile row)
    const int bn  = (tid & 31) << 2;   // 0..124 (B tile col)
    const int gn  = col0 + bn;
    const bool bok = gn < N;

    unsigned long long acc[8][4];
    #pragma unroll
    for (int i = 0; i < 8; i++)
        #pragma unroll
        for (int j = 0; j < 4; j++) acc[i][j] = 0ull;

    const int T = K >> 4;
    const float4 z4 = make_float4(0.f, 0.f, 0.f, 0.f);
    const float* Abase = A + (row0 + am) * K + ak0;

    // prologue: tile 0
    float4 ra0 = *(const float4*)(Abase);
    float4 ra1 = *(const float4*)(Abase + 8);
    float4 rb0 = bok ? *(const float4*)(Bm + bk * N + gn) : z4;
    float4 rb1 = bok ? *(const float4*)(Bm + (bk + 8) * N + gn) : z4;
    As[0][ak0 + 0][am] = ra0.x; As[0][ak0 + 1][am] = ra0.y;
    As[0][ak0 + 2][am] = ra0.z; As[0][ak0 + 3][am] = ra0.w;
    As[0][ak0 + 8][am] = ra1.x; As[0][ak0 + 9][am] = ra1.y;
    As[0][ak0 +10][am] = ra1.z; As[0][ak0 +11][am] = ra1.w;
    *(float4*)&Bs[0][bk][bn]     = rb0;
    *(float4*)&Bs[0][bk + 8][bn] = rb1;
    __syncthreads();

    for (int kt = 0; kt < T; kt++) {
        const int cur = kt & 1;
        if (kt + 1 < T) {
            const float* Ap = Abase + (kt + 1) * 16;
            ra0 = *(const float4*)(Ap);
            ra1 = *(const float4*)(Ap + 8);
            const int gk = (kt + 1) * 16;
            rb0 = bok ? *(const float4*)(Bm + (gk + bk) * N + gn) : z4;
            rb1 = bok ? *(const float4*)(Bm + (gk + bk + 8) * N + gn) : z4;
        }
        #pragma unroll
        for (int kk = 0; kk < 16; kk++) {
            float4 a0 = *(const float4*)&As[cur][kk][ty * 8];
            float4 a1 = *(const float4*)&As[cur][kk][ty * 8 + 4];
            ulonglong2 bp0 = *(const ulonglong2*)&Bs[cur][kk][tx * 8];
            ulonglong2 bp1 = *(const ulonglong2*)&Bs[cur][kk][tx * 8 + 4];
            unsigned long long b2[4] = { bp0.x, bp0.y, bp1.x, bp1.y };
            unsigned long long a2[8] = {
                bcast2(a0.x), bcast2(a0.y), bcast2(a0.z), bcast2(a0.w),
                bcast2(a1.x), bcast2(a1.y), bcast2(a1.z), bcast2(a1.w)
            };
            #pragma unroll
            for (int i = 0; i < 8; i++)
                #pragma unroll
                for (int j = 0; j < 4; j++)
                    fma2(acc[i][j], a2[i], b2[j]);
        }
        if (kt + 1 < T) {
            const int nxt = cur ^ 1;
            As[nxt][ak0 + 0][am] = ra0.x; As[nxt][ak0 + 1][am] = ra0.y;
            As[nxt][ak0 + 2][am] = ra0.z; As[nxt][ak0 + 3][am] = ra0.w;
            As[nxt][ak0 + 8][am] = ra1.x; As[nxt][ak0 + 9][am] = ra1.y;
            As[nxt][ak0 +10][am] = ra1.z; As[nxt][ak0 +11][am] = ra1.w;
            *(float4*)&Bs[nxt][bk][bn]     = rb0;
            *(float4*)&Bs[nxt][bk + 8][bn] = rb1;
        }
        __syncthreads();
    }

    // epilogue
    if (MODE == 4) {
        const int jblk = row0 >> 9;
        const int off  = (jblk == 0) ? o0 : (jblk == 1) ? o1 : (jblk == 2) ? o2 : o3;
        const int hmask = (1 << hdshift) - 1;
        #pragma unroll
        for (int i = 0; i < 8; i++) {
            const int r = row0 + ty * 8 + i;
            const int n = r & (NN - 1);
            #pragma unroll
            for (int j = 0; j < 4; j++) {
                #pragma unroll
                for (int h = 0; h < 2; h++) {
                    const int cc = col0 + tx * 8 + 2 * j + h;
                    if (cc < N) {
                        float v = h ? __uint_as_float((unsigned)(acc[i][j] >> 32))
                                    : __uint_as_float((unsigned)(acc[i][j]));
                        const int b = cc >> hdshift;
                        const int c = cc & hmask;
                        C[(n * BB + b) * Ktot + off + c] = v;
                    }
                }
            }
        }
    } else {
        #pragma unroll
        for (int i = 0; i < 8; i++) {
            const int r = row0 + ty * 8 + i;
            #pragma unroll
            for (int j = 0; j < 4; j++) {
                #pragma unroll
                for (int h = 0; h < 2; h++) {
                    const int cc = col0 + tx * 8 + 2 * j + h;
                    if (cc >= N) continue;
                    float v = h ? __uint_as_float((unsigned)(acc[i][j] >> 32))
                                : __uint_as_float((unsigned)(acc[i][j]));
                    if (MODE == 0) {
                        C[r * N + cc] = v;
                    } else if (MODE == 1) {
                        C[r * N + cc] = 2.f * v - ((r == cc) ? 1.f : 0.f);
                    } else if (MODE == 2) {
                        v = 1.f / (1.f + expf(-(v + bias[cc])));
                        if (cc < splitN) C [r * splitN + cc]            = v;
                        else             C2[r * splitN + (cc - splitN)] = v;
                    } else { // MODE 3
                        C[r * N + cc] = tanhf(v + bias[cc]);
                    }
                }
            }
        }
    }
}

// ---------------- small kernels ----------------
__global__ void k_zero(float* p, int n) {
    int i = blockIdx.x * blockDim.x + threadIdx.x;
    if (i < n) p[i] = 0.f;
}

__global__ void k_copy(const float* __restrict__ s, float* __restrict__ d, int n) {
    int i = blockIdx.x * blockDim.x + threadIdx.x;
    if (i < n) d[i] = s[i];
}

// e = We(512x20) @ Memory(20x64)
__global__ void k_eW(const float* __restrict__ We, const float* __restrict__ Mem,
                     float* __restrict__ e) {
    int idx = blockIdx.x * blockDim.x + threadIdx.x;
    if (idx >= NN * 64) return;
    int n = idx >> 6, d = idx & 63;
    float s = 0.f;
    #pragma unroll
    for (int k = 0; k < 20; k++) s += We[n * 20 + k] * Mem[k * 64 + d];
    e[idx] = s;
}

// g = softmax(relu(ea @ eb^T)) rows; one block per row, 128 threads
__global__ void k_gsoftmax(const float* __restrict__ ea, const float* __restrict__ eb,
                           float* __restrict__ g) {
    __shared__ float er[64];
    __shared__ float buf[NN];
    __shared__ float red[128];
    int n = blockIdx.x, tid = threadIdx.x;
    if (tid < 64) er[tid] = ea[n * 64 + tid];
    __syncthreads();
    for (int m = tid; m < NN; m += 128) {
        float s = 0.f;
        #pragma unroll
        for (int d = 0; d < 64; d++) s += er[d] * eb[m * 64 + d];
        buf[m] = s > 0.f ? s : 0.f;
    }
    __syncthreads();
    float mx = -1e30f;
    for (int m = tid; m < NN; m += 128) mx = fmaxf(mx, buf[m]);
    red[tid] = mx; __syncthreads();
    for (int s = 64; s > 0; s >>= 1) { if (tid < s) red[tid] = fmaxf(red[tid], red[tid + s]); __syncthreads(); }
    mx = red[0]; __syncthreads();
    float sm = 0.f;
    for (int m = tid; m < NN; m += 128) { float e = expf(buf[m] - mx); buf[m] = e; sm += e; }
    red[tid] = sm; __syncthreads();
    for (int s = 64; s > 0; s >>= 1) { if (tid < s) red[tid] += red[tid + s]; __syncthreads(); }
    float inv = 1.f / red[0];
    for (int m = tid; m < NN; m += 128) g[n * NN + m] = buf[m] * inv;
}

// x (B,1,N,L) -> xT (n, l, b)
__global__ void k_xT(const float* __restrict__ x, float* __restrict__ xT) {
    int idx = blockIdx.x * blockDim.x + threadIdx.x;
    if (idx >= BB * NN * LL) return;
    int l = idx % LL;
    int n = (idx / LL) % NN;
    int b = idx / (LL * NN);
    xT[(n * LL + l) * BB + b] = x[idx];
}

// fill encoder x-channels of xg for step l (cols {0,65,130,195,260,325}, stride KENC_P)
__global__ void k_fill_enc_x(float* __restrict__ xg, const float* __restrict__ xT,
                             const float* __restrict__ GX, int l) {
    int row = blockIdx.x * blockDim.x + threadIdx.x;
    if (row >= ROWS) return;
    int n = row >> 6, b = row & 63;
    float xv = xT[(n * LL + l) * BB + b];
    float* p = xg + row * KENC_P;
    p[0]   = xv;
    p[195] = xv;
    p[65]  = GX[(0 * NN + n) * (LL * BB) + l * BB + b];
    p[130] = GX[(1 * NN + n) * (LL * BB) + l * BB + b];
    p[260] = GX[(2 * NN + n) * (LL * BB) + l * BB + b];
    p[325] = GX[(3 * NN + n) * (LL * BB) + l * BB + b];
}

// fill identity-support h-channels of xg (blocks k=0 and k=3)
__global__ void k_fill_h_id(float* __restrict__ xg, const float* __restrict__ h,
                            int hdshift, int Ktot, int off0, int off3, int total) {
    int i = blockIdx.x * blockDim.x + threadIdx.x;
    if (i >= total) return;
    int row = i >> hdshift;
    int c   = i & ((1 << hdshift) - 1);
    float v = h[i];
    float* p = xg + row * Ktot;
    p[off0 + c] = v;
    p[off3 + c] = v;
}

// fill decoder go + ycov channels for step t (ycov: row-sum-1 trick -> broadcast)
__global__ void k_fill_dec(float* __restrict__ xg, const float* __restrict__ go,
                           const float* __restrict__ Ggo, const float* __restrict__ tt, int t) {
    int row = blockIdx.x * blockDim.x + threadIdx.x;
    if (row >= ROWS) return;
    int n = row >> 6, b = row & 63;
    float* p = xg + row * KDEC_P;
    float gv = go[row];
    p[0]   = gv;
    p[402] = gv;
    p[134] = Ggo[(0 * NN + n) * BB + b];
    p[268] = Ggo[(1 * NN + n) * BB + b];
    p[536] = Ggo[(2 * NN + n) * BB + b];
    p[670] = Ggo[(3 * NN + n) * BB + b];
    #pragma unroll
    for (int c = 0; c < 5; c++) {
        float v = tt[(b * 5 + c) * HH + t];
        p[1 + c] = v; p[135 + c] = v; p[269 + c] = v;
        p[403 + c] = v; p[537 + c] = v; p[671 + c] = v;
    }
}

__global__ void k_zh(const float* __restrict__ z, const float* __restrict__ h,
                     float* __restrict__ zh, int n) {
    int i = blockIdx.x * blockDim.x + threadIdx.x;
    if (i < n) zh[i] = z[i] * h[i];
}

__global__ void k_hupd(const float* __restrict__ r, const float* __restrict__ hc,
                       float* __restrict__ h, int n) {
    int i = blockIdx.x * blockDim.x + threadIdx.x;
    if (i < n) { float rv = r[i]; h[i] = rv * h[i] + (1.f - rv) * hc[i]; }
}

// attention over memory; one block per (n,b) row, 64 threads
__global__ void k_attn(const float* __restrict__ h, const float* __restrict__ Wq,
                       const float* __restrict__ Mem, float* __restrict__ hde) {
    __shared__ float hr[64];
    __shared__ float q[64];
    __shared__ float sc[20];
    int row = blockIdx.x, tid = threadIdx.x;
    hr[tid] = h[row * 64 + tid];
    __syncthreads();
    float s = 0.f;
    #pragma unroll
    for (int c = 0; c < 64; c++) s += hr[c] * Wq[c * 64 + tid];
    q[tid] = s;
    __syncthreads();
    if (tid < 20) {
        float v = 0.f;
        #pragma unroll
        for (int c = 0; c < 64; c++) v += q[c] * Mem[tid * 64 + c];
        sc[tid] = v;
    }
    __syncthreads();
    if (tid == 0) {
        float mx = -1e30f;
        for (int j = 0; j < 20; j++) mx = fmaxf(mx, sc[j]);
        float sm = 0.f;
        for (int j = 0; j < 20; j++) { sc[j] = expf(sc[j] - mx); sm += sc[j]; }
        float inv = 1.f / sm;
        for (int j = 0; j < 20; j++) sc[j] *= inv;
    }
    __syncthreads();
    float ha = 0.f;
    #pragma unroll
    for (int j = 0; j < 20; j++) ha += sc[j] * Mem[j * 64 + tid];
    hde[row * 128 + tid]      = hr[tid];
    hde[row * 128 + 64 + tid] = ha;
}

// decoder h update + projection + output write; one block per row, 128 threads
__global__ void k_hupd_dec(const float* __restrict__ r, const float* __restrict__ hc,
                           float* __restrict__ h, const float* __restrict__ pW,
                           const float* __restrict__ pb, float* __restrict__ go,
                           float* __restrict__ out, int t) {
    __shared__ float red[128];
    int row = blockIdx.x, c = threadIdx.x;
    int i = row * 128 + c;
    float rv = r[i];
    float hn = rv * h[i] + (1.f - rv) * hc[i];
    h[i] = hn;
    red[c] = hn * pW[c];
    __syncthreads();
    for (int s = 64; s > 0; s >>= 1) { if (c < s) red[c] += red[c + s]; __syncthreads(); }
    if (c == 0) {
        float g = red[0] + pb[0];
        go[row] = g;
        int n = row >> 6, b = row & 63;
        out[(b * NN + n) * HH + t] = g;
    }
}

// ---------------- host side ----------------
static void launch_gemm(int mode, const float* A, const float* B, float* C,
                        int M, int N, int K,
                        const float* bias = nullptr, float* C2 = nullptr, int splitN = 0,
                        int hdshift = 0, int Ktot = 0,
                        int o0 = 0, int o1 = 0, int o2 = 0, int o3 = 0)
{
    dim3 grid((N + 127) / 128, M / 128);
    switch (mode) {
        case 0: sgemm<0><<<grid, 256>>>(A, B, C, M, N, K, bias, C2, splitN, hdshift, Ktot, o0, o1, o2, o3); break;
        case 1: sgemm<1><<<grid, 256>>>(A, B, C, M, N, K, bias, C2, splitN, hdshift, Ktot, o0, o1, o2, o3); break;
        case 2: sgemm<2><<<grid, 256>>>(A, B, C, M, N, K, bias, C2, splitN, hdshift, Ktot, o0, o1, o2, o3); break;
        case 3: sgemm<3><<<grid, 256>>>(A, B, C, M, N, K, bias, C2, splitN, hdshift, Ktot, o0, o1, o2, o3); break;
        case 4: sgemm<4><<<grid, 256>>>(A, B, C, M, N, K, bias, C2, splitN, hdshift, Ktot, o0, o1, o2, o3); break;
    }
}

extern "C" void kernel_launch(void* const* d_in, const int* in_sizes, int n_in,
                              void* d_out, int out_size)
{
    const float* x   = (const float*)d_in[0];
    const float* tt  = (const float*)d_in[3];
    const float* Mem = (const float*)d_in[5];
    const float* Wq  = (const float*)d_in[6];
    const float* We1 = (const float*)d_in[7];
    const float* We2 = (const float*)d_in[8];
    const float* egW = (const float*)d_in[9];
    const float* egb = (const float*)d_in[10];
    const float* euW = (const float*)d_in[11];
    const float* eub = (const float*)d_in[12];
    const float* dgW = (const float*)d_in[13];
    const float* dgb = (const float*)d_in[14];
    const float* duW = (const float*)d_in[15];
    const float* dub = (const float*)d_in[16];
    const float* pW  = (const float*)d_in[17];
    const float* pb  = (const float*)d_in[18];
    float* out = (float*)d_out;

    float *S, *e1, *e2, *xT, *GX, *xg, *henc, *hdec, *z, *r, *hc, *zh, *go, *Ggo;
    float *egWp, *euWp, *dgWp, *duWp;
    cudaGetSymbolAddress((void**)&S,    g_S);
    cudaGetSymbolAddress((void**)&e1,   g_e1);
    cudaGetSymbolAddress((void**)&e2,   g_e2);
    cudaGetSymbolAddress((void**)&xT,   g_xT);
    cudaGetSymbolAddress((void**)&GX,   g_GX);
    cudaGetSymbolAddress((void**)&xg,   g_xg);
    cudaGetSymbolAddress((void**)&henc, g_henc);
    cudaGetSymbolAddress((void**)&hdec, g_hdec);
    cudaGetSymbolAddress((void**)&z,    g_z);
    cudaGetSymbolAddress((void**)&r,    g_r);
    cudaGetSymbolAddress((void**)&hc,   g_hc);
    cudaGetSymbolAddress((void**)&zh,   g_zh);
    cudaGetSymbolAddress((void**)&go,   g_go);
    cudaGetSymbolAddress((void**)&Ggo,  g_Ggo);
    cudaGetSymbolAddress((void**)&egWp, g_egWp);
    cudaGetSymbolAddress((void**)&euWp, g_euWp);
    cudaGetSymbolAddress((void**)&dgWp, g_dgWp);
    cudaGetSymbolAddress((void**)&duWp, g_duWp);

    // --- padded weight copies (pad rows stay zero from zero-init) ---
    k_copy<<<(KENC * 128 + 255) / 256, 256>>>(egW, egWp, KENC * 128);
    k_copy<<<(KENC * 64  + 255) / 256, 256>>>(euW, euWp, KENC * 64);
    k_copy<<<(KDEC * 256 + 255) / 256, 256>>>(dgW, dgWp, KDEC * 256);
    k_copy<<<(KDEC * 128 + 255) / 256, 256>>>(duW, duWp, KDEC * 128);

    // --- supports ---
    k_eW<<<(NN * 64 + 255) / 256, 256>>>(We1, Mem, e1);
    k_eW<<<(NN * 64 + 255) / 256, 256>>>(We2, Mem, e2);
    k_gsoftmax<<<NN, 128>>>(e1, e2, S);                   // g1 -> block 0
    k_gsoftmax<<<NN, 128>>>(e2, e1, S + 2 * NN * NN);     // g2 -> block 2
    launch_gemm(1, S,               S,               S + 1 * NN * NN, NN, NN, NN); // 2g1^2-I
    launch_gemm(1, S + 2 * NN * NN, S + 2 * NN * NN, S + 3 * NN * NN, NN, NN, NN); // 2g2^2-I

    // --- encoder x precompute ---
    k_xT<<<(BB * NN * LL + 255) / 256, 256>>>(x, xT);
    launch_gemm(0, S, xT, GX, 4 * NN, LL * BB, NN);

    // --- init states ---
    k_zero<<<(ROWS * RNN + 255) / 256, 256>>>(henc, ROWS * RNN);
    k_zero<<<(ROWS + 255) / 256, 256>>>(go, ROWS);

    // --- encoder ---
    for (int l = 0; l < LL; l++) {
        k_fill_enc_x<<<ROWS / 256, 256>>>(xg, xT, GX, l);
        k_fill_h_id<<<(ROWS * RNN) / 256, 256>>>(xg, henc, 6, KENC_P, 1, 196, ROWS * RNN);
        launch_gemm(4, S, henc, xg, 4 * NN, BB * RNN, NN, nullptr, nullptr, 0,
                    6, KENC_P, 66, 131, 261, 326);
        launch_gemm(2, xg, egWp, z, ROWS, 2 * RNN, KENC_P, egb, r, RNN);
        k_zh<<<(ROWS * RNN) / 256, 256>>>(z, henc, zh, ROWS * RNN);
        k_fill_h_id<<<(ROWS * RNN) / 256, 256>>>(xg, zh, 6, KENC_P, 1, 196, ROWS * RNN);
        launch_gemm(4, S, zh, xg, 4 * NN, BB * RNN, NN, nullptr, nullptr, 0,
                    6, KENC_P, 66, 131, 261, 326);
        launch_gemm(3, xg, euWp, hc, ROWS, RNN, KENC_P, eub);
        k_hupd<<<(ROWS * RNN) / 256, 256>>>(r, hc, henc, ROWS * RNN);
    }

    // --- memory attention -> decoder initial hidden ---
    k_attn<<<ROWS, 64>>>(henc, Wq, Mem, hdec);

    // --- decoder ---
    for (int t = 0; t < HH; t++) {
        launch_gemm(0, S, go, Ggo, 4 * NN, BB, NN);
        k_fill_dec<<<ROWS / 256, 256>>>(xg, go, Ggo, tt, t);
        k_fill_h_id<<<(ROWS * DDEC) / 256, 256>>>(xg, hdec, 7, KDEC_P, 6, 408, ROWS * DDEC);
        launch_gemm(4, S, hdec, xg, 4 * NN, BB * DDEC, NN, nullptr, nullptr, 0,
                    7, KDEC_P, 140, 274, 542, 676);
        launch_gemm(2, xg, dgWp, z, ROWS, 2 * DDEC, KDEC_P, dgb, r, DDEC);
        k_zh<<<(ROWS * DDEC) / 256, 256>>>(z, hdec, zh, ROWS * DDEC);
        k_fill_h_id<<<(ROWS * DDEC) / 256, 256>>>(xg, zh, 7, KDEC_P, 6, 408, ROWS * DDEC);
        launch_gemm(4, S, zh, xg, 4 * NN, BB * DDEC, NN, nullptr, nullptr, 0,
                    7, KDEC_P, 140, 274, 542, 676);
        launch_gemm(3, xg, duWp, hc, ROWS, DDEC, KDEC_P, dub);
        k_hupd_dec<<<ROWS, 128>>>(r, hc, hdec, pW, pb, go, out, t);
    }
}

// round 3
// speedup vs baseline: 1.5619x; 1.2108x over previous
#include <cuda_runtime.h>
#include <cuda_bf16.h>
#include <math.h>

// ---------------- problem constants ----------------
#define NN   512
#define BB   64
#define LL   12
#define HH   12
#define RNN  64
#define DDEC 128
#define KENC 390        // logical enc feature count
#define KDEC 804        // logical dec feature count
#define SECE 416        // enc section (pad to /32)
#define SECD 832        // dec section
#define KPE  (3*SECE)   // 1248
#define KPD  (3*SECD)   // 2496
#define KGC  (3*NN)     // 1536 (graph conv K')
#define ROWS (NN*BB)    // 32768

typedef __nv_bfloat16 bf16;

// ---------------- scratch (device globals; zero-init, no allocation) ----------------
__device__ float g_S[4*NN*NN];
__device__ float g_e1[NN*64];
__device__ float g_e2[NN*64];
__device__ float g_xT[NN*LL*BB];
__device__ float g_GX[4*NN*LL*BB];
__device__ float g_henc[ROWS*RNN];
__device__ float g_hdec[ROWS*DDEC];
__device__ float g_z [ROWS*DDEC];
__device__ float g_r [ROWS*DDEC];
__device__ float g_hc[ROWS*DDEC];
__device__ float g_zh[ROWS*DDEC];
__device__ float g_go[ROWS];
__device__ float g_Ggo[4*NN*BB];
// bf16 split operands
__device__ bf16 g_Sbig [4*NN*KGC];       // A: [hi|lo|hi], 2048 x 1536
__device__ bf16 g_hB   [KGC*BB*DDEC];    // B: [hi|hi|lo], up to 1536 x 8192 (reused)
__device__ bf16 g_xgE  [ROWS*KPE];       // enc feature A (pads stay 0)
__device__ bf16 g_xgD  [ROWS*KPD];       // dec feature A
__device__ bf16 g_egWB [KPE*128];
__device__ bf16 g_euWB [KPE*64];
__device__ bf16 g_dgWB [KPD*256];
__device__ bf16 g_duWB [KPD*128];

// ---------------- helpers ----------------
__device__ __forceinline__ void split2(float v, bf16 &h, bf16 &l) {
    h = __float2bfloat16(v);
    l = __float2bfloat16(v - __bfloat162float(h));
}
// A-layout triple write: [hi | lo | hi] at offsets off, sec+off, 2sec+off
__device__ __forceinline__ void store3(bf16* p, int off, int sec, float v) {
    bf16 h, l; split2(v, h, l);
    p[off] = h; p[sec + off] = l; p[2 * sec + off] = h;
}
__device__ __forceinline__ void fma2(unsigned long long &d, unsigned long long a, unsigned long long b) {
    asm("fma.rn.f32x2 %0, %1, %2, %0;" : "+l"(d) : "l"(a), "l"(b));
}
__device__ __forceinline__ unsigned long long bcast2(float x) {
    unsigned long long r;
    asm("mov.b64 %0, {%1, %1};" : "=l"(r) : "f"(x));
    return r;
}

// ================= bf16 tensor-core GEMM, 128x128x32, m16n8k16 =================
// A: row-major M x Kp (bf16), B: row-major Kp x N (bf16). M%128==0, Kp%32==0.
// MODE 2: v=sigmoid(acc+bias[c]); c<splitN -> Cz else Cr (fp32, stride splitN)
// MODE 3: C[r*ldC+c] = tanh(acc+bias[c])     (fp32)
// MODE 4: graph-conv scatter into xg (bf16 triple): row=j*512+n, col=b*hd+c ->
//         xg[(n*BB+b)*(3*sec) + off_j + c] (hi/lo/hi)
template<int MODE>
__global__ void __launch_bounds__(256)
bgemm(const bf16* __restrict__ A, const bf16* __restrict__ Bm, void* __restrict__ Cv,
      int M, int N, int Kp, const float* __restrict__ bias, float* __restrict__ C2,
      int splitN, int ldC, int hdshift, int sec, int o0, int o1, int o2, int o3)
{
    __shared__ __align__(16) bf16 As[2][128 * 40];
    __shared__ __align__(16) bf16 Bs[2][32 * 136];

    const int tid  = threadIdx.x;
    const int lane = tid & 31;
    const int warp = tid >> 5;
    const int wm   = warp & 1;   // 0..1
    const int wn   = warp >> 1;  // 0..3
    const int row0 = blockIdx.y * 128;
    const int col0 = blockIdx.x * 128;

    float acc[4][4][4];
    #pragma unroll
    for (int i = 0; i < 4; i++)
        #pragma unroll
        for (int j = 0; j < 4; j++)
            #pragma unroll
            for (int g = 0; g < 4; g++) acc[i][j][g] = 0.f;

    // load indices
    const int aq0 = tid * 2;              // two 16B chunks for A
    const int ar0 = aq0 >> 2, ac0 = (aq0 & 3) * 8;
    const int ar1 = (aq0 + 1) >> 2, ac1 = ((aq0 + 1) & 3) * 8;
    const int br0 = aq0 >> 4, bc0 = (aq0 & 15) * 8;
    const int br1 = (aq0 + 1) >> 4, bc1 = ((aq0 + 1) & 15) * 8;

    const int T = Kp >> 5;
    int4 pa0, pa1, pb0, pb1;
    const int4 z4 = make_int4(0, 0, 0, 0);

    // prologue
    pa0 = *(const int4*)(A + (size_t)(row0 + ar0) * Kp + ac0);
    pa1 = *(const int4*)(A + (size_t)(row0 + ar1) * Kp + ac1);
    pb0 = (col0 + bc0 < N) ? *(const int4*)(Bm + (size_t)br0 * N + col0 + bc0) : z4;
    pb1 = (col0 + bc1 < N) ? *(const int4*)(Bm + (size_t)br1 * N + col0 + bc1) : z4;
    *(int4*)&As[0][ar0 * 40 + ac0] = pa0;
    *(int4*)&As[0][ar1 * 40 + ac1] = pa1;
    *(int4*)&Bs[0][br0 * 136 + bc0] = pb0;
    *(int4*)&Bs[0][br1 * 136 + bc1] = pb1;
    __syncthreads();

    for (int kt = 0; kt < T; kt++) {
        const int cur = kt & 1;
        if (kt + 1 < T) {
            const int k0 = (kt + 1) * 32;
            pa0 = *(const int4*)(A + (size_t)(row0 + ar0) * Kp + k0 + ac0);
            pa1 = *(const int4*)(A + (size_t)(row0 + ar1) * Kp + k0 + ac1);
            pb0 = (col0 + bc0 < N) ? *(const int4*)(Bm + (size_t)(k0 + br0) * N + col0 + bc0) : z4;
            pb1 = (col0 + bc1 < N) ? *(const int4*)(Bm + (size_t)(k0 + br1) * N + col0 + bc1) : z4;
        }
        #pragma unroll
        for (int kk = 0; kk < 2; kk++) {
            unsigned af[4][4], bfg[4][2];
            #pragma unroll
            for (int i = 0; i < 4; i++) {
                const bf16* p = &As[cur][(wm * 64 + i * 16 + (lane & 15)) * 40 + kk * 16 + (lane >> 4) * 8];
                unsigned addr = (unsigned)__cvta_generic_to_shared(p);
                asm volatile("ldmatrix.sync.aligned.m8n8.x4.shared.b16 {%0,%1,%2,%3}, [%4];"
                             : "=r"(af[i][0]), "=r"(af[i][1]), "=r"(af[i][2]), "=r"(af[i][3])
                             : "r"(addr));
            }
            #pragma unroll
            for (int j = 0; j < 4; j++) {
                const bf16* p = &Bs[cur][(kk * 16 + (lane & 15)) * 136 + wn * 32 + j * 8];
                unsigned addr = (unsigned)__cvta_generic_to_shared(p);
                asm volatile("ldmatrix.sync.aligned.m8n8.x2.trans.shared.b16 {%0,%1}, [%2];"
                             : "=r"(bfg[j][0]), "=r"(bfg[j][1]) : "r"(addr));
            }
            #pragma unroll
            for (int i = 0; i < 4; i++)
                #pragma unroll
                for (int j = 0; j < 4; j++)
                    asm volatile(
                        "mma.sync.aligned.m16n8k16.row.col.f32.bf16.bf16.f32 "
                        "{%0,%1,%2,%3}, {%4,%5,%6,%7}, {%8,%9}, {%0,%1,%2,%3};"
                        : "+f"(acc[i][j][0]), "+f"(acc[i][j][1]), "+f"(acc[i][j][2]), "+f"(acc[i][j][3])
                        : "r"(af[i][0]), "r"(af[i][1]), "r"(af[i][2]), "r"(af[i][3]),
                          "r"(bfg[j][0]), "r"(bfg[j][1]));
        }
        if (kt + 1 < T) {
            const int nxt = cur ^ 1;
            *(int4*)&As[nxt][ar0 * 40 + ac0] = pa0;
            *(int4*)&As[nxt][ar1 * 40 + ac1] = pa1;
            *(int4*)&Bs[nxt][br0 * 136 + bc0] = pb0;
            *(int4*)&Bs[nxt][br1 * 136 + bc1] = pb1;
        }
        __syncthreads();
    }

    // epilogue
    if (MODE == 4) {
        bf16* C = (bf16*)Cv;
        const int jblk = row0 >> 9;
        const int off  = (jblk == 0) ? o0 : (jblk == 1) ? o1 : (jblk == 2) ? o2 : o3;
        const int hmask = (1 << hdshift) - 1;
        const int Ktot = 3 * sec;
        #pragma unroll
        for (int i = 0; i < 4; i++)
            #pragma unroll
            for (int j = 0; j < 4; j++)
                #pragma unroll
                for (int g = 0; g < 4; g++) {
                    int rr = row0 + wm * 64 + i * 16 + (lane >> 2) + ((g >> 1) << 3);
                    int cc = col0 + wn * 32 + j * 8 + ((lane & 3) << 1) + (g & 1);
                    if (cc < N) {
                        int n = rr & (NN - 1);
                        int b = cc >> hdshift;
                        int c = cc & hmask;
                        store3(C + (size_t)(n * BB + b) * Ktot, off + c, sec, acc[i][j][g]);
                    }
                }
    } else {
        float* C = (float*)Cv;
        #pragma unroll
        for (int i = 0; i < 4; i++)
            #pragma unroll
            for (int j = 0; j < 4; j++)
                #pragma unroll
                for (int g = 0; g < 4; g++) {
                    int rr = row0 + wm * 64 + i * 16 + (lane >> 2) + ((g >> 1) << 3);
                    int cc = col0 + wn * 32 + j * 8 + ((lane & 3) << 1) + (g & 1);
                    if (cc >= N) continue;
                    float v = acc[i][j][g];
                    if (MODE == 2) {
                        v = 1.f / (1.f + expf(-(v + bias[cc])));
                        if (cc < splitN) C [(size_t)rr * splitN + cc]           = v;
                        else             C2[(size_t)rr * splitN + (cc - splitN)] = v;
                    } else { // MODE 3
                        C[(size_t)rr * ldC + cc] = tanhf(v + bias[cc]);
                    }
                }
    }
}

// ================= fp32 f32x2 SGEMM (small GEMMs only) =====================
// MODE 0: plain, MODE 1: 2*acc - I
template<int MODE>
__global__ void __launch_bounds__(256)
sgemm(const float* __restrict__ A, const float* __restrict__ Bm, float* __restrict__ C,
      int M, int N, int K)
{
    __shared__ __align__(16) float As[2][16][132];
    __shared__ __align__(16) float Bsh[2][16][132];
    const int tid = threadIdx.x;
    const int tx  = tid & 15;
    const int ty  = tid >> 4;
    const int row0 = blockIdx.y * 128;
    const int col0 = blockIdx.x * 128;

    const int am  = tid >> 1;
    const int ak0 = (tid & 1) << 2;
    const int bk  = tid >> 5;
    const int bn  = (tid & 31) << 2;
    const int gn  = col0 + bn;
    const bool bok = gn < N;

    unsigned long long acc[8][4];
    #pragma unroll
    for (int i = 0; i < 8; i++)
        #pragma unroll
        for (int j = 0; j < 4; j++) acc[i][j] = 0ull;

    const int T = K >> 4;
    const float4 z4 = make_float4(0.f, 0.f, 0.f, 0.f);
    const float* Abase = A + (size_t)(row0 + am) * K + ak0;

    float4 ra0 = *(const float4*)(Abase);
    float4 ra1 = *(const float4*)(Abase + 8);
    float4 rb0 = bok ? *(const float4*)(Bm + (size_t)bk * N + gn) : z4;
    float4 rb1 = bok ? *(const float4*)(Bm + (size_t)(bk + 8) * N + gn) : z4;
    As[0][ak0 + 0][am] = ra0.x; As[0][ak0 + 1][am] = ra0.y;
    As[0][ak0 + 2][am] = ra0.z; As[0][ak0 + 3][am] = ra0.w;
    As[0][ak0 + 8][am] = ra1.x; As[0][ak0 + 9][am] = ra1.y;
    As[0][ak0 +10][am] = ra1.z; As[0][ak0 +11][am] = ra1.w;
    *(float4*)&Bsh[0][bk][bn]     = rb0;
    *(float4*)&Bsh[0][bk + 8][bn] = rb1;
    __syncthreads();

    for (int kt = 0; kt < T; kt++) {
        const int cur = kt & 1;
        if (kt + 1 < T) {
            const float* Ap = Abase + (kt + 1) * 16;
            ra0 = *(const float4*)(Ap);
            ra1 = *(const float4*)(Ap + 8);
            const int gk = (kt + 1) * 16;
            rb0 = bok ? *(const float4*)(Bm + (size_t)(gk + bk) * N + gn) : z4;
            rb1 = bok ? *(const float4*)(Bm + (size_t)(gk + bk + 8) * N + gn) : z4;
        }
        #pragma unroll
        for (int kk = 0; kk < 16; kk++) {
            float4 a0 = *(const float4*)&As[cur][kk][ty * 8];
            float4 a1 = *(const float4*)&As[cur][kk][ty * 8 + 4];
            ulonglong2 bp0 = *(const ulonglong2*)&Bsh[cur][kk][tx * 8];
            ulonglong2 bp1 = *(const ulonglong2*)&Bsh[cur][kk][tx * 8 + 4];
            unsigned long long b2[4] = { bp0.x, bp0.y, bp1.x, bp1.y };
            unsigned long long a2[8] = {
                bcast2(a0.x), bcast2(a0.y), bcast2(a0.z), bcast2(a0.w),
                bcast2(a1.x), bcast2(a1.y), bcast2(a1.z), bcast2(a1.w)
            };
            #pragma unroll
            for (int i = 0; i < 8; i++)
                #pragma unroll
                for (int j = 0; j < 4; j++)
                    fma2(acc[i][j], a2[i], b2[j]);
        }
        if (kt + 1 < T) {
            const int nxt = cur ^ 1;
            As[nxt][ak0 + 0][am] = ra0.x; As[nxt][ak0 + 1][am] = ra0.y;
            As[nxt][ak0 + 2][am] = ra0.z; As[nxt][ak0 + 3][am] = ra0.w;
            As[nxt][ak0 + 8][am] = ra1.x; As[nxt][ak0 + 9][am] = ra1.y;
            As[nxt][ak0 +10][am] = ra1.z; As[nxt][ak0 +11][am] = ra1.w;
            *(float4*)&Bsh[nxt][bk][bn]     = rb0;
            *(float4*)&Bsh[nxt][bk + 8][bn] = rb1;
        }
        __syncthreads();
    }

    #pragma unroll
    for (int i = 0; i < 8; i++) {
        const int r = row0 + ty * 8 + i;
        #pragma unroll
        for (int j = 0; j < 4; j++) {
            #pragma unroll
            for (int h = 0; h < 2; h++) {
                const int cc = col0 + tx * 8 + 2 * j + h;
                if (cc >= N) continue;
                float v = h ? __uint_as_float((unsigned)(acc[i][j] >> 32))
                            : __uint_as_float((unsigned)(acc[i][j]));
                if (MODE == 0) C[(size_t)r * N + cc] = v;
                else           C[(size_t)r * N + cc] = 2.f * v - ((r == cc) ? 1.f : 0.f);
            }
        }
    }
}

// ---------------- small kernels ----------------
__global__ void k_zero(float* p, int n) {
    int i = blockIdx.x * blockDim.x + threadIdx.x;
    if (i < n) p[i] = 0.f;
}

// split fp32 (M x K) -> A-layout bf16 (M x 3K): [hi | lo | hi]
__global__ void k_splitA(const float* __restrict__ in, bf16* __restrict__ out, int K, int total) {
    int i = blockIdx.x * blockDim.x + threadIdx.x;
    if (i >= total) return;
    int m = i / K, k = i - m * K;
    bf16 h, l; split2(in[i], h, l);
    bf16* p = out + (size_t)m * 3 * K;
    p[k] = h; p[K + k] = l; p[2 * K + k] = h;
}

// split fp32 (Kreal x N) -> B-layout bf16 (3*Ksec x N): [hi | hi | lo]
__global__ void k_splitB(const float* __restrict__ in, bf16* __restrict__ out,
                         int Kreal, int Ksec, int N, int total) {
    int i = blockIdx.x * blockDim.x + threadIdx.x;
    if (i >= total) return;
    int k = i / N, j = i - k * N;
    bf16 h, l; split2(in[i], h, l);
    out[(size_t)k * N + j]                 = h;
    out[(size_t)(Ksec + k) * N + j]        = h;
    out[(size_t)(2 * Ksec + k) * N + j]    = l;
}

// e = We(512x20) @ Memory(20x64)
__global__ void k_eW(const float* __restrict__ We, const float* __restrict__ Mem,
                     float* __restrict__ e) {
    int idx = blockIdx.x * blockDim.x + threadIdx.x;
    if (idx >= NN * 64) return;
    int n = idx >> 6, d = idx & 63;
    float s = 0.f;
    #pragma unroll
    for (int k = 0; k < 20; k++) s += We[n * 20 + k] * Mem[k * 64 + d];
    e[idx] = s;
}

__global__ void k_gsoftmax(const float* __restrict__ ea, const float* __restrict__ eb,
                           float* __restrict__ g) {
    __shared__ float er[64];
    __shared__ float buf[NN];
    __shared__ float red[128];
    int n = blockIdx.x, tid = threadIdx.x;
    if (tid < 64) er[tid] = ea[n * 64 + tid];
    __syncthreads();
    for (int m = tid; m < NN; m += 128) {
        float s = 0.f;
        #pragma unroll
        for (int d = 0; d < 64; d++) s += er[d] * eb[m * 64 + d];
        buf[m] = s > 0.f ? s : 0.f;
    }
    __syncthreads();
    float mx = -1e30f;
    for (int m = tid; m < NN; m += 128) mx = fmaxf(mx, buf[m]);
    red[tid] = mx; __syncthreads();
    for (int s = 64; s > 0; s >>= 1) { if (tid < s) red[tid] = fmaxf(red[tid], red[tid + s]); __syncthreads(); }
    mx = red[0]; __syncthreads();
    float sm = 0.f;
    for (int m = tid; m < NN; m += 128) { float e = expf(buf[m] - mx); buf[m] = e; sm += e; }
    red[tid] = sm; __syncthreads();
    for (int s = 64; s > 0; s >>= 1) { if (tid < s) red[tid] += red[tid + s]; __syncthreads(); }
    float inv = 1.f / red[0];
    for (int m = tid; m < NN; m += 128) g[n * NN + m] = buf[m] * inv;
}

__global__ void k_xT(const float* __restrict__ x, float* __restrict__ xT) {
    int idx = blockIdx.x * blockDim.x + threadIdx.x;
    if (idx >= BB * NN * LL) return;
    int l = idx % LL;
    int n = (idx / LL) % NN;
    int b = idx / (LL * NN);
    xT[(n * LL + l) * BB + b] = x[idx];
}

// fill encoder x-channels of xgE for step l (triples)
__global__ void k_fill_enc_x(bf16* __restrict__ xg, const float* __restrict__ xT,
                             const float* __restrict__ GX, int l) {
    int row = blockIdx.x * blockDim.x + threadIdx.x;
    if (row >= ROWS) return;
    int n = row >> 6, b = row & 63;
    bf16* p = xg + (size_t)row * KPE;
    float xv = xT[(n * LL + l) * BB + b];
    store3(p, 0, SECE, xv);
    store3(p, 195, SECE, xv);
    store3(p, 65,  SECE, GX[(size_t)(0 * NN + n) * (LL * BB) + l * BB + b]);
    store3(p, 130, SECE, GX[(size_t)(1 * NN + n) * (LL * BB) + l * BB + b]);
    store3(p, 260, SECE, GX[(size_t)(2 * NN + n) * (LL * BB) + l * BB + b]);
    store3(p, 325, SECE, GX[(size_t)(3 * NN + n) * (LL * BB) + l * BB + b]);
}

// fill identity-support h-channels (blocks 0 and 3) as triples
__global__ void k_fill_h_id(bf16* __restrict__ xg, const float* __restrict__ h,
                            int hdshift, int sec, int off0, int off3, int total) {
    int i = blockIdx.x * blockDim.x + threadIdx.x;
    if (i >= total) return;
    int row = i >> hdshift;
    int c   = i & ((1 << hdshift) - 1);
    float v = h[i];
    bf16* p = xg + (size_t)row * 3 * sec;
    store3(p, off0 + c, sec, v);
    store3(p, off3 + c, sec, v);
}

// fill decoder go + ycov channels for step t
__global__ void k_fill_dec(bf16* __restrict__ xg, const float* __restrict__ go,
                           const float* __restrict__ Ggo, const float* __restrict__ tt, int t) {
    int row = blockIdx.x * blockDim.x + threadIdx.x;
    if (row >= ROWS) return;
    int n = row >> 6, b = row & 63;
    bf16* p = xg + (size_t)row * KPD;
    float gv = go[row];
    store3(p, 0,   SECD, gv);
    store3(p, 402, SECD, gv);
    store3(p, 134, SECD, Ggo[(0 * NN + n) * BB + b]);
    store3(p, 268, SECD, Ggo[(1 * NN + n) * BB + b]);
    store3(p, 536, SECD, Ggo[(2 * NN + n) * BB + b]);
    store3(p, 670, SECD, Ggo[(3 * NN + n) * BB + b]);
    #pragma unroll
    for (int c = 0; c < 5; c++) {
        float v = tt[(b * 5 + c) * HH + t];
        store3(p, 1 + c,   SECD, v); store3(p, 135 + c, SECD, v);
        store3(p, 269 + c, SECD, v); store3(p, 403 + c, SECD, v);
        store3(p, 537 + c, SECD, v); store3(p, 671 + c, SECD, v);
    }
}

__global__ void k_zh(const float* __restrict__ z, const float* __restrict__ h,
                     float* __restrict__ zh, int n) {
    int i = blockIdx.x * blockDim.x + threadIdx.x;
    if (i < n) zh[i] = z[i] * h[i];
}

__global__ void k_hupd(const float* __restrict__ r, const float* __restrict__ hc,
                       float* __restrict__ h, int n) {
    int i = blockIdx.x * blockDim.x + threadIdx.x;
    if (i < n) { float rv = r[i]; h[i] = rv * h[i] + (1.f - rv) * hc[i]; }
}

__global__ void k_attn(const float* __restrict__ h, const float* __restrict__ Wq,
                       const float* __restrict__ Mem, float* __restrict__ hde) {
    __shared__ float hr[64];
    __shared__ float q[64];
    __shared__ float sc[20];
    int row = blockIdx.x, tid = threadIdx.x;
    hr[tid] = h[row * 64 + tid];
    __syncthreads();
    float s = 0.f;
    #pragma unroll
    for (int c = 0; c < 64; c++) s += hr[c] * Wq[c * 64 + tid];
    q[tid] = s;
    __syncthreads();
    if (tid < 20) {
        float v = 0.f;
        #pragma unroll
        for (int c = 0; c < 64; c++) v += q[c] * Mem[tid * 64 + c];
        sc[tid] = v;
    }
    __syncthreads();
    if (tid == 0) {
        float mx = -1e30f;
        for (int j = 0; j < 20; j++) mx = fmaxf(mx, sc[j]);
        float sm = 0.f;
        for (int j = 0; j < 20; j++) { sc[j] = expf(sc[j] - mx); sm += sc[j]; }
        float inv = 1.f / sm;
        for (int j = 0; j < 20; j++) sc[j] *= inv;
    }
    __syncthreads();
    float ha = 0.f;
    #pragma unroll
    for (int j = 0; j < 20; j++) ha += sc[j] * Mem[j * 64 + tid];
    hde[row * 128 + tid]      = hr[tid];
    hde[row * 128 + 64 + tid] = ha;
}

__global__ void k_hupd_dec(const float* __restrict__ r, const float* __restrict__ hc,
                           float* __restrict__ h, const float* __restrict__ pW,
                           const float* __restrict__ pb, float* __restrict__ go,
                           float* __restrict__ out, int t) {
    __shared__ float red[128];
    int row = blockIdx.x, c = threadIdx.x;
    int i = row * 128 + c;
    float rv = r[i];
    float hn = rv * h[i] + (1.f - rv) * hc[i];
    h[i] = hn;
    red[c] = hn * pW[c];
    __syncthreads();
    for (int s = 64; s > 0; s >>= 1) { if (c < s) red[c] += red[c + s]; __syncthreads(); }
    if (c == 0) {
        float g = red[0] + pb[0];
        go[row] = g;
        int n = row >> 6, b = row & 63;
        out[(b * NN + n) * HH + t] = g;
    }
}

// ---------------- host side ----------------
static void bgemm_launch(int mode, const bf16* A, const bf16* B, void* C,
                         int M, int N, int Kp,
                         const float* bias = nullptr, float* C2 = nullptr,
                         int splitN = 0, int ldC = 0, int hdshift = 0, int sec = 0,
                         int o0 = 0, int o1 = 0, int o2 = 0, int o3 = 0)
{
    dim3 grid((N + 127) / 128, M / 128);
    switch (mode) {
        case 2: bgemm<2><<<grid, 256>>>(A, B, C, M, N, Kp, bias, C2, splitN, ldC, hdshift, sec, o0, o1, o2, o3); break;
        case 3: bgemm<3><<<grid, 256>>>(A, B, C, M, N, Kp, bias, C2, splitN, ldC, hdshift, sec, o0, o1, o2, o3); break;
        case 4: bgemm<4><<<grid, 256>>>(A, B, C, M, N, Kp, bias, C2, splitN, ldC, hdshift, sec, o0, o1, o2, o3); break;
    }
}

extern "C" void kernel_launch(void* const* d_in, const int* in_sizes, int n_in,
                              void* d_out, int out_size)
{
    const float* x   = (const float*)d_in[0];
    const float* tt  = (const float*)d_in[3];
    const float* Mem = (const float*)d_in[5];
    const float* Wq  = (const float*)d_in[6];
    const float* We1 = (const float*)d_in[7];
    const float* We2 = (const float*)d_in[8];
    const float* egW = (const float*)d_in[9];
    const float* egb = (const float*)d_in[10];
    const float* euW = (const float*)d_in[11];
    const float* eub = (const float*)d_in[12];
    const float* dgW = (const float*)d_in[13];
    const float* dgb = (const float*)d_in[14];
    const float* duW = (const float*)d_in[15];
    const float* dub = (const float*)d_in[16];
    const float* pW  = (const float*)d_in[17];
    const float* pb  = (const float*)d_in[18];
    float* out = (float*)d_out;

    float *S, *e1, *e2, *xT, *GX, *henc, *hdec, *z, *r, *hc, *zh, *go, *Ggo;
    bf16 *Sbig, *hB, *xgE, *xgD, *egWB, *euWB, *dgWB, *duWB;
    cudaGetSymbolAddress((void**)&S,    g_S);
    cudaGetSymbolAddress((void**)&e1,   g_e1);
    cudaGetSymbolAddress((void**)&e2,   g_e2);
    cudaGetSymbolAddress((void**)&xT,   g_xT);
    cudaGetSymbolAddress((void**)&GX,   g_GX);
    cudaGetSymbolAddress((void**)&henc, g_henc);
    cudaGetSymbolAddress((void**)&hdec, g_hdec);
    cudaGetSymbolAddress((void**)&z,    g_z);
    cudaGetSymbolAddress((void**)&r,    g_r);
    cudaGetSymbolAddress((void**)&hc,   g_hc);
    cudaGetSymbolAddress((void**)&zh,   g_zh);
    cudaGetSymbolAddress((void**)&go,   g_go);
    cudaGetSymbolAddress((void**)&Ggo,  g_Ggo);
    cudaGetSymbolAddress((void**)&Sbig, g_Sbig);
    cudaGetSymbolAddress((void**)&hB,   g_hB);
    cudaGetSymbolAddress((void**)&xgE,  g_xgE);
    cudaGetSymbolAddress((void**)&xgD,  g_xgD);
    cudaGetSymbolAddress((void**)&egWB, g_egWB);
    cudaGetSymbolAddress((void**)&euWB, g_euWB);
    cudaGetSymbolAddress((void**)&dgWB, g_dgWB);
    cudaGetSymbolAddress((void**)&duWB, g_duWB);

    // --- weight splits (pad rows of big buffers stay zero) ---
    k_splitB<<<(KENC * 128 + 255) / 256, 256>>>(egW, egWB, KENC, SECE, 128, KENC * 128);
    k_splitB<<<(KENC * 64  + 255) / 256, 256>>>(euW, euWB, KENC, SECE, 64,  KENC * 64);
    k_splitB<<<(KDEC * 256 + 255) / 256, 256>>>(dgW, dgWB, KDEC, SECD, 256, KDEC * 256);
    k_splitB<<<(KDEC * 128 + 255) / 256, 256>>>(duW, duWB, KDEC, SECD, 128, KDEC * 128);

    // --- supports (fp32) ---
    k_eW<<<(NN * 64 + 255) / 256, 256>>>(We1, Mem, e1);
    k_eW<<<(NN * 64 + 255) / 256, 256>>>(We2, Mem, e2);
    k_gsoftmax<<<NN, 128>>>(e1, e2, S);
    k_gsoftmax<<<NN, 128>>>(e2, e1, S + 2 * NN * NN);
    {
        dim3 g1(NN / 128, NN / 128);
        sgemm<1><<<g1, 256>>>(S,               S,               S + 1 * NN * NN, NN, NN, NN);
        sgemm<1><<<g1, 256>>>(S + 2 * NN * NN, S + 2 * NN * NN, S + 3 * NN * NN, NN, NN, NN);
    }
    k_splitA<<<(4 * NN * NN + 255) / 256, 256>>>(S, Sbig, NN, 4 * NN * NN);

    // --- encoder x precompute (fp32) ---
    k_xT<<<(BB * NN * LL + 255) / 256, 256>>>(x, xT);
    {
        dim3 g2((LL * BB + 127) / 128, 4 * NN / 128);
        sgemm<0><<<g2, 256>>>(S, xT, GX, 4 * NN, LL * BB, NN);
    }

    // --- init states ---
    k_zero<<<(ROWS * RNN + 255) / 256, 256>>>(henc, ROWS * RNN);
    k_zero<<<(ROWS + 255) / 256, 256>>>(go, ROWS);

    // --- encoder ---
    for (int l = 0; l < LL; l++) {
        k_fill_enc_x<<<ROWS / 256, 256>>>(xgE, xT, GX, l);
        k_fill_h_id<<<(ROWS * RNN) / 256, 256>>>(xgE, henc, 6, SECE, 1, 196, ROWS * RNN);
        k_splitB<<<(ROWS * RNN + 255) / 256, 256>>>(henc, hB, NN, NN, BB * RNN, ROWS * RNN);
        bgemm_launch(4, Sbig, hB, xgE, 4 * NN, BB * RNN, KGC,
                     nullptr, nullptr, 0, 0, 6, SECE, 66, 131, 261, 326);
        bgemm_launch(2, xgE, egWB, z, ROWS, 2 * RNN, KPE, egb, r, RNN);
        k_zh<<<(ROWS * RNN) / 256, 256>>>(z, henc, zh, ROWS * RNN);
        k_fill_h_id<<<(ROWS * RNN) / 256, 256>>>(xgE, zh, 6, SECE, 1, 196, ROWS * RNN);
        k_splitB<<<(ROWS * RNN + 255) / 256, 256>>>(zh, hB, NN, NN, BB * RNN, ROWS * RNN);
        bgemm_launch(4, Sbig, hB, xgE, 4 * NN, BB * RNN, KGC,
                     nullptr, nullptr, 0, 0, 6, SECE, 66, 131, 261, 326);
        bgemm_launch(3, xgE, euWB, hc, ROWS, RNN, KPE, eub, nullptr, 0, RNN);
        k_hupd<<<(ROWS * RNN) / 256, 256>>>(r, hc, henc, ROWS * RNN);
    }

    // --- memory attention -> decoder initial hidden ---
    k_attn<<<ROWS, 64>>>(henc, Wq, Mem, hdec);

    // --- decoder ---
    for (int t = 0; t < HH; t++) {
        {
            dim3 g3(1, 4 * NN / 128);
            sgemm<0><<<g3, 256>>>(S, go, Ggo, 4 * NN, BB, NN);
        }
        k_fill_dec<<<ROWS / 256, 256>>>(xgD, go, Ggo, tt, t);
        k_fill_h_id<<<(ROWS * DDEC) / 256, 256>>>(xgD, hdec, 7, SECD, 6, 408, ROWS * DDEC);
        k_splitB<<<(ROWS * DDEC + 255) / 256, 256>>>(hdec, hB, NN, NN, BB * DDEC, ROWS * DDEC);
        bgemm_launch(4, Sbig, hB, xgD, 4 * NN, BB * DDEC, KGC,
                     nullptr, nullptr, 0, 0, 7, SECD, 140, 274, 542, 676);
        bgemm_launch(2, xgD, dgWB, z, ROWS, 2 * DDEC, KPD, dgb, r, DDEC);
        k_zh<<<(ROWS * DDEC) / 256, 256>>>(z, hdec, zh, ROWS * DDEC);
        k_fill_h_id<<<(ROWS * DDEC) / 256, 256>>>(xgD, zh, 7, SECD, 6, 408, ROWS * DDEC);
        k_splitB<<<(ROWS * DDEC + 255) / 256, 256>>>(zh, hB, NN, NN, BB * DDEC, ROWS * DDEC);
        bgemm_launch(4, Sbig, hB, xgD, 4 * NN, BB * DDEC, KGC,
                     nullptr, nullptr, 0, 0, 7, SECD, 140, 274, 542, 676);
        bgemm_launch(3, xgD, duWB, hc, ROWS, DDEC, KPD, dub, nullptr, 0, DDEC);
        k_hupd_dec<<<ROWS, 128>>>(r, hc, hdec, pW, pb, go, out, t);
    }
}